// round 1
// baseline (speedup 1.0000x reference)
#include <cuda_runtime.h>
#include <math.h>
#include <stdint.h>

// Problem constants
#define B_  8
#define T_  1024
#define D_  512
#define H_  8
#define DK_ 64
#define BT_ 8192      // B*T
#define BH_ 64        // B*H

// ---------------- scratch (device globals; no allocation allowed) ----------------
__device__ float g_proj[6][BT_ * D_];        // 0:qm 1:qc 2:km 3:kc 4:vm 5:vc
__device__ float g_qcat[BH_ * 128 * T_];     // [bh][dcat][t]  dcat: 0..63 mean, 64..127 sqrt(cov)
__device__ float g_kcat[BH_ * 128 * T_];
__device__ float g_vm2[BH_ * T_ * DK_];      // [bh][s][d]
__device__ float g_vc2[BH_ * T_ * DK_];
__device__ float g_bq[BH_ * T_];             // |qm|^2 + sum(qc_raw)
__device__ float g_bk[BH_ * T_];
__device__ float g_cm[BT_ * D_];             // attention out (B,T,D)
__device__ float g_cc[BT_ * D_];

struct ProjArgs { const float* A[6]; const float* W[6]; const float* bias[6]; };
struct OutArgs  { const float* W[2]; const float* bias[2]; };

// ---------------- SGEMM: C[8192,512] = A[8192,512] @ W[512,512]^T + bias ----------------
// BM=BN=128, BK=16, 256 threads, 8x8 split micro-tile (conflict-free LDS.128 reads)
__device__ __forceinline__ void gemm_core(const float* __restrict__ A,
                                          const float* __restrict__ W,
                                          const float* __restrict__ bias,
                                          float* __restrict__ C)
{
    __shared__ float As[16][128];
    __shared__ float Ws[16][128];
    const int K = 512;
    const int tid = threadIdx.x;
    const int tx = tid & 15, ty = tid >> 4;
    const int lr = tid >> 2;            // 0..63
    const int lk = (tid & 3) << 2;      // 0,4,8,12

    const float* Ap = A + (size_t)(blockIdx.y * 128) * K;
    const float* Wp = W + (size_t)(blockIdx.x * 128) * K;

    float acc[8][8];
#pragma unroll
    for (int i = 0; i < 8; i++)
#pragma unroll
        for (int j = 0; j < 8; j++) acc[i][j] = 0.f;

    for (int kt = 0; kt < K; kt += 16) {
        float4 a0 = *(const float4*)(Ap + (size_t)lr * K + kt + lk);
        float4 a1 = *(const float4*)(Ap + (size_t)(lr + 64) * K + kt + lk);
        float4 w0 = *(const float4*)(Wp + (size_t)lr * K + kt + lk);
        float4 w1 = *(const float4*)(Wp + (size_t)(lr + 64) * K + kt + lk);
        __syncthreads();
        As[lk + 0][lr] = a0.x; As[lk + 1][lr] = a0.y; As[lk + 2][lr] = a0.z; As[lk + 3][lr] = a0.w;
        As[lk + 0][lr + 64] = a1.x; As[lk + 1][lr + 64] = a1.y; As[lk + 2][lr + 64] = a1.z; As[lk + 3][lr + 64] = a1.w;
        Ws[lk + 0][lr] = w0.x; Ws[lk + 1][lr] = w0.y; Ws[lk + 2][lr] = w0.z; Ws[lk + 3][lr] = w0.w;
        Ws[lk + 0][lr + 64] = w1.x; Ws[lk + 1][lr + 64] = w1.y; Ws[lk + 2][lr + 64] = w1.z; Ws[lk + 3][lr + 64] = w1.w;
        __syncthreads();
#pragma unroll
        for (int k = 0; k < 16; k++) {
            float4 af0 = *(const float4*)&As[k][4 * ty];
            float4 af1 = *(const float4*)&As[k][64 + 4 * ty];
            float4 wf0 = *(const float4*)&Ws[k][4 * tx];
            float4 wf1 = *(const float4*)&Ws[k][64 + 4 * tx];
            float a[8] = {af0.x, af0.y, af0.z, af0.w, af1.x, af1.y, af1.z, af1.w};
            float w[8] = {wf0.x, wf0.y, wf0.z, wf0.w, wf1.x, wf1.y, wf1.z, wf1.w};
#pragma unroll
            for (int i = 0; i < 8; i++)
#pragma unroll
                for (int j = 0; j < 8; j++) acc[i][j] += a[i] * w[j];
        }
    }

    const int col0 = blockIdx.x * 128 + 4 * tx;
    float4 b0 = *(const float4*)(bias + col0);
    float4 b1 = *(const float4*)(bias + col0 + 64);
#pragma unroll
    for (int i = 0; i < 8; i++) {
        int r = blockIdx.y * 128 + ((i < 4) ? (4 * ty + i) : (64 + 4 * ty + (i - 4)));
        float4 o0 = make_float4(acc[i][0] + b0.x, acc[i][1] + b0.y, acc[i][2] + b0.z, acc[i][3] + b0.w);
        float4 o1 = make_float4(acc[i][4] + b1.x, acc[i][5] + b1.y, acc[i][6] + b1.z, acc[i][7] + b1.w);
        *(float4*)(C + (size_t)r * 512 + col0)      = o0;
        *(float4*)(C + (size_t)r * 512 + col0 + 64) = o1;
    }
}

__global__ void __launch_bounds__(256, 2) proj_gemm(ProjArgs pa)
{
    int z = blockIdx.z;
    gemm_core(pa.A[z], pa.W[z], pa.bias[z], &g_proj[z][0]);
}

__global__ void __launch_bounds__(256, 2) out_gemm(OutArgs oa, float* __restrict__ out)
{
    int z = blockIdx.z;
    gemm_core(z ? g_cc : g_cm, oa.W[z], oa.bias[z], out + (size_t)z * BT_ * D_);
}

// ---------------- per-(bh,t) bias sums ----------------
__global__ void rowsum_kernel()
{
    int gw = (blockIdx.x * blockDim.x + threadIdx.x) >> 5;
    int lane = threadIdx.x & 31;
    if (gw >= BH_ * T_) return;
    int bh = gw >> 10, t = gw & 1023;
    int b = bh >> 3, h = bh & 7;
    size_t base = (size_t)(b * 1024 + t) * 512 + h * 64;
    float s0 = 0.f, s1 = 0.f, s2 = 0.f, s3 = 0.f;
#pragma unroll
    for (int i = 0; i < 2; i++) {
        int d = lane + 32 * i;
        float a = g_proj[0][base + d]; s0 += a * a;   // |qm|^2
        s1 += g_proj[1][base + d];                     // sum qc (raw)
        float c = g_proj[2][base + d]; s2 += c * c;    // |km|^2
        s3 += g_proj[3][base + d];                     // sum kc (raw)
    }
#pragma unroll
    for (int o = 16; o; o >>= 1) {
        s0 += __shfl_xor_sync(0xffffffffu, s0, o);
        s1 += __shfl_xor_sync(0xffffffffu, s1, o);
        s2 += __shfl_xor_sync(0xffffffffu, s2, o);
        s3 += __shfl_xor_sync(0xffffffffu, s3, o);
    }
    if (lane == 0) { g_bq[gw] = s0 + s1; g_bk[gw] = s2 + s3; }
}

// ---------------- pack Q/K into d-major [bh][128][T] (cov half gets sqrt(clip)) ----------------
__global__ void pack_qk()
{
    __shared__ float tile[32][33];
    int bh = blockIdx.z, b = bh >> 3, h = bh & 7;
    int t0 = blockIdx.y * 32;
    int zz = blockIdx.x;              // 0..3 Q, 4..7 K
    bool isK = (zz >= 4);
    int dc0 = (zz & 3) * 32;
    const float* srcM = isK ? g_proj[2] : g_proj[0];
    const float* srcC = isK ? g_proj[3] : g_proj[1];
    float* dst = (isK ? g_kcat : g_qcat) + (size_t)bh * 128 * T_;
    int tid = threadIdx.x;

    for (int e = tid; e < 1024; e += 256) {
        int tl = e >> 5, dl = e & 31;
        int dcat = dc0 + dl;
        float v;
        size_t rb = (size_t)(b * 1024 + t0 + tl) * 512 + h * 64;
        if (dcat < 64) v = srcM[rb + dcat];
        else           v = sqrtf(fmaxf(srcC[rb + dcat - 64], 1e-24f));
        tile[tl][dl] = v;
    }
    __syncthreads();
    for (int e = tid; e < 1024; e += 256) {
        int dl = e >> 5, tl = e & 31;
        dst[(size_t)(dc0 + dl) * T_ + t0 + tl] = tile[tl][dl];
    }
}

// ---------------- pack V into [bh][s][64] ----------------
__global__ void pack_v()
{
    int idx = blockIdx.x * 256 + threadIdx.x;   // < BH_*T_*DK_
    int d = idx & 63;
    int s = (idx >> 6) & 1023;
    int bh = idx >> 16;
    int b = bh >> 3, h = bh & 7;
    size_t src = (size_t)(b * 1024 + s) * 512 + h * 64 + d;
    g_vm2[idx] = g_proj[4][src];
    g_vc2[idx] = g_proj[5][src];
}

// ---------------- fused attention ----------------
// CTA = (bh, 32-row tile). smem: scores[32][1024] + q[128][32] + k/v[128][128] + bk[128]
#define TR 32
#define ATTN_SMEM ((32 * 1024 + 128 * 32 + 128 * 128 + 128) * 4)

__device__ __forceinline__ float wredmax(float v)
{
#pragma unroll
    for (int o = 16; o; o >>= 1) v = fmaxf(v, __shfl_xor_sync(0xffffffffu, v, o));
    return v;
}
__device__ __forceinline__ float wredsum(float v)
{
#pragma unroll
    for (int o = 16; o; o >>= 1) v += __shfl_xor_sync(0xffffffffu, v, o);
    return v;
}

__global__ void __launch_bounds__(256, 1) attn_kernel(const float* __restrict__ gammas)
{
    extern __shared__ float smem[];
    float* sc  = smem;                  // 32*1024
    float* qs  = sc + 32 * 1024;        // [d][t] 128*32
    float* ks  = qs + 128 * 32;         // [d][s] 128*128 (reused for V tiles)
    float* bks = ks + 128 * 128;        // 128

    const int bh = blockIdx.y;
    const int tile = (int)gridDim.x - 1 - (int)blockIdx.x;   // heavy tiles first
    const int t0 = tile * TR;
    const int tid = threadIdx.x;
    const int lane = tid & 31, warp = tid >> 5;
    const int NT = (t0 + TR + 127) / 128;
    const int Smax = NT * 128;
    const int b = bh >> 3, h = bh & 7;

    const float* Qc = g_qcat + (size_t)bh * 128 * T_;
    const float* Kc = g_kcat + (size_t)bh * 128 * T_;

    // ---- load Q tile (d-major) ----
#pragma unroll
    for (int it = 0; it < 4; it++) {
        int idx = it * 256 + tid;               // 1024 float4
        int d = idx >> 3, t4 = (idx & 7) * 4;
        float4 v = *(const float4*)(Qc + (size_t)d * T_ + t0 + t4);
        *(float4*)(qs + d * 32 + t4) = v;
    }
    // per-thread bq for its 4 rows (score phase mapping)
    const int tgrp = warp;          // rows 4*warp..4*warp+3
    const int sgrp = lane;          // cols 4*lane..4*lane+3 within 128-s tile
    float bq4[4];
    {
        const float* bqp = g_bq + bh * T_ + t0 + 4 * tgrp;
        bq4[0] = bqp[0]; bq4[1] = bqp[1]; bq4[2] = bqp[2]; bq4[3] = bqp[3];
    }

    // ---- score phase ----
    for (int st = 0; st < NT; st++) {
        const int S0 = st * 128;
        __syncthreads();
#pragma unroll
        for (int it = 0; it < 16; it++) {
            int idx = it * 256 + tid;           // 4096 float4
            int d = idx >> 5, s4 = (idx & 31) * 4;
            float4 v = *(const float4*)(Kc + (size_t)d * T_ + S0 + s4);
            *(float4*)(ks + d * 128 + s4) = v;
        }
        if (tid < 128) bks[tid] = g_bk[bh * T_ + S0 + tid];
        __syncthreads();

        float acc[4][4];
#pragma unroll
        for (int i = 0; i < 4; i++)
#pragma unroll
            for (int j = 0; j < 4; j++) acc[i][j] = 0.f;

#pragma unroll 8
        for (int d = 0; d < 128; d++) {
            float4 qf = *(const float4*)(qs + d * 32 + 4 * tgrp);
            float4 kf = *(const float4*)(ks + d * 128 + 4 * sgrp);
            float q[4] = {qf.x, qf.y, qf.z, qf.w};
            float k[4] = {kf.x, kf.y, kf.z, kf.w};
#pragma unroll
            for (int i = 0; i < 4; i++)
#pragma unroll
                for (int j = 0; j < 4; j++) acc[i][j] += q[i] * k[j];
        }
        float bk0 = bks[4 * sgrp + 0], bk1 = bks[4 * sgrp + 1];
        float bk2 = bks[4 * sgrp + 2], bk3 = bks[4 * sgrp + 3];
#pragma unroll
        for (int i = 0; i < 4; i++) {
            float4 o;
            o.x = (2.f * acc[i][0] - bq4[i] - bk0) * 0.125f;
            o.y = (2.f * acc[i][1] - bq4[i] - bk1) * 0.125f;
            o.z = (2.f * acc[i][2] - bq4[i] - bk2) * 0.125f;
            o.w = (2.f * acc[i][3] - bq4[i] - bk3) * 0.125f;
            *(float4*)(sc + (4 * tgrp + i) * 1024 + S0 + 4 * sgrp) = o;
        }
    }
    __syncthreads();

    // ---- softmax -> cumsum decay -> softmax (warp per row) ----
    float g = gammas[h];
    float gamma = -(fmaxf(g, 0.f) + log1pf(__expf(-fabsf(g))));   // -softplus

    for (int r = warp; r < TR; r += 8) {
        const int tg = t0 + r;
        float* row = sc + r * 1024;
        const int L = tg + 1;

        float m = -3.4e38f;
        for (int s = lane; s < L; s += 32) m = fmaxf(m, row[s]);
        m = wredmax(m);

        float sum = 0.f;
        for (int s = lane; s < L; s += 32) sum += __expf(row[s] - m);
        sum = wredsum(sum);
        const float inv = 1.f / sum;

        // cumsum of first softmax + decay + rescale scores
        float carry = 0.f, m2 = -3.4e38f;
        const int nch = (L + 31) >> 5;
        for (int c = 0; c < nch; c++) {
            int s = c * 32 + lane;
            bool v = (s < L);
            float x = v ? row[s] : 0.f;
            float e = v ? __expf(x - m) * inv : 0.f;
            float scan = e;
#pragma unroll
            for (int o = 1; o < 32; o <<= 1) {
                float n = __shfl_up_sync(0xffffffffu, scan, o);
                if (lane >= o) scan += n;
            }
            float cum = carry + scan;                               // inclusive
            carry += __shfl_sync(0xffffffffu, scan, 31);
            if (v) {
                float pos = (float)(tg - s);                        // |t-s|, s<=t
                float ds = sqrtf(fmaxf((1.f - cum) * pos, 0.f));    // disttot==1
                float eff = __expf(ds * gamma);
                eff = fminf(fmaxf(eff, 1e-5f), 1e5f);
                float y = x * eff;
                row[s] = y;
                m2 = fmaxf(m2, y);
            }
        }
        m2 = wredmax(m2);

        float s2 = 0.f;
        for (int s = lane; s < L; s += 32) {
            float e = __expf(row[s] - m2);
            row[s] = e;
            s2 += e;
        }
        s2 = wredsum(s2);
        const float inv2 = (tg == 0) ? 0.f : 1.f / s2;              // zero_pad row 0
        for (int s = lane; s < Smax; s += 32)
            row[s] = (s < L) ? row[s] * inv2 : 0.f;
    }
    __syncthreads();

    // ---- PV: out_mean = P @ vm ; out_cov = P^2 @ vc ----
    float am[2][4], ac[2][4];
#pragma unroll
    for (int i = 0; i < 2; i++)
#pragma unroll
        for (int j = 0; j < 4; j++) { am[i][j] = 0.f; ac[i][j] = 0.f; }

    const int dgrp = tid & 15;       // d = 4*dgrp
    const int tg2 = tid >> 4;        // rows 2*tg2, 2*tg2+1
    float* vsm = ks;                 // [s][64]
    float* vsc = ks + 128 * 64;
    const float* Vm = g_vm2 + (size_t)bh * T_ * DK_;
    const float* Vc = g_vc2 + (size_t)bh * T_ * DK_;
    const float* prow0 = sc + (2 * tg2) * 1024;
    const float* prow1 = sc + (2 * tg2 + 1) * 1024;

    for (int st = 0; st < NT; st++) {
        const int S0 = st * 128;
        __syncthreads();
#pragma unroll
        for (int it = 0; it < 8; it++) {
            int idx = it * 256 + tid;           // 2048 float4 per tensor
            int s = idx >> 4, d4 = (idx & 15) * 4;
            *(float4*)(vsm + s * 64 + d4) = *(const float4*)(Vm + (size_t)(S0 + s) * 64 + d4);
            *(float4*)(vsc + s * 64 + d4) = *(const float4*)(Vc + (size_t)(S0 + s) * 64 + d4);
        }
        __syncthreads();
#pragma unroll 4
        for (int s = 0; s < 128; s++) {
            float p0 = prow0[S0 + s];
            float p1 = prow1[S0 + s];
            float4 vm4 = *(const float4*)(vsm + s * 64 + 4 * dgrp);
            float4 vc4 = *(const float4*)(vsc + s * 64 + 4 * dgrp);
            float p0s = p0 * p0, p1s = p1 * p1;
            am[0][0] += p0 * vm4.x; am[0][1] += p0 * vm4.y; am[0][2] += p0 * vm4.z; am[0][3] += p0 * vm4.w;
            am[1][0] += p1 * vm4.x; am[1][1] += p1 * vm4.y; am[1][2] += p1 * vm4.z; am[1][3] += p1 * vm4.w;
            ac[0][0] += p0s * vc4.x; ac[0][1] += p0s * vc4.y; ac[0][2] += p0s * vc4.z; ac[0][3] += p0s * vc4.w;
            ac[1][0] += p1s * vc4.x; ac[1][1] += p1s * vc4.y; ac[1][2] += p1s * vc4.z; ac[1][3] += p1s * vc4.w;
        }
    }

    // write to (B,T,D)
    size_t obase = (size_t)(b * 1024 + t0 + 2 * tg2) * 512 + h * 64 + 4 * dgrp;
    *(float4*)(g_cm + obase)       = make_float4(am[0][0], am[0][1], am[0][2], am[0][3]);
    *(float4*)(g_cm + obase + 512) = make_float4(am[1][0], am[1][1], am[1][2], am[1][3]);
    *(float4*)(g_cc + obase)       = make_float4(ac[0][0], ac[0][1], ac[0][2], ac[0][3]);
    *(float4*)(g_cc + obase + 512) = make_float4(ac[1][0], ac[1][1], ac[1][2], ac[1][3]);
}

// ---------------- launch ----------------
extern "C" void kernel_launch(void* const* d_in, const int* in_sizes, int n_in,
                              void* d_out, int out_size)
{
    const float* q_mean  = (const float*)d_in[0];
    const float* q_cov   = (const float*)d_in[1];
    const float* k_mean  = (const float*)d_in[2];
    const float* k_cov   = (const float*)d_in[3];
    const float* v_mean  = (const float*)d_in[4];
    const float* v_cov   = (const float*)d_in[5];
    const float* Wk_mean = (const float*)d_in[6];
    const float* bk_mean = (const float*)d_in[7];
    const float* Wk_cov  = (const float*)d_in[8];
    const float* bk_cov  = (const float*)d_in[9];
    const float* Wv_mean = (const float*)d_in[10];
    const float* bv_mean = (const float*)d_in[11];
    const float* Wv_cov  = (const float*)d_in[12];
    const float* bv_cov  = (const float*)d_in[13];
    const float* Wo_mean = (const float*)d_in[14];
    const float* bo_mean = (const float*)d_in[15];
    const float* Wo_cov  = (const float*)d_in[16];
    const float* bo_cov  = (const float*)d_in[17];
    const float* gammas  = (const float*)d_in[18];
    float* out = (float*)d_out;

    ProjArgs pa;
    pa.A[0] = q_mean; pa.W[0] = Wk_mean; pa.bias[0] = bk_mean;   // qm (kq_same)
    pa.A[1] = q_cov;  pa.W[1] = Wk_cov;  pa.bias[1] = bk_cov;    // qc
    pa.A[2] = k_mean; pa.W[2] = Wk_mean; pa.bias[2] = bk_mean;   // km
    pa.A[3] = k_cov;  pa.W[3] = Wk_cov;  pa.bias[3] = bk_cov;    // kc
    pa.A[4] = v_mean; pa.W[4] = Wv_mean; pa.bias[4] = bv_mean;   // vm
    pa.A[5] = v_cov;  pa.W[5] = Wv_cov;  pa.bias[5] = bv_cov;    // vc

    proj_gemm<<<dim3(4, 64, 6), 256>>>(pa);
    rowsum_kernel<<<(BH_ * T_ * 32) / 256, 256>>>();
    pack_qk<<<dim3(8, 32, 64), 256>>>();
    pack_v<<<(BH_ * T_ * DK_) / 256, 256>>>();

    cudaFuncSetAttribute(attn_kernel, cudaFuncAttributeMaxDynamicSharedMemorySize, ATTN_SMEM);
    attn_kernel<<<dim3(32, 64), 256, ATTN_SMEM>>>(gammas);

    OutArgs oa;
    oa.W[0] = Wo_mean; oa.bias[0] = bo_mean;
    oa.W[1] = Wo_cov;  oa.bias[1] = bo_cov;
    out_gemm<<<dim3(4, 64, 2), 256>>>(oa, out);
}

// round 4
// speedup vs baseline: 1.2403x; 1.2403x over previous
#include <cuda_runtime.h>
#include <cuda_bf16.h>
#include <math.h>
#include <stdint.h>

// Problem constants
#define B_  8
#define T_  1024
#define D_  512
#define H_  8
#define DK_ 64
#define BT_ 8192      // B*T
#define BH_ 64        // B*H

// single dynamic-smem symbol (attention kernel only)
extern __shared__ char dsmem[];

// ---------------- scratch (device globals; no allocation allowed) ----------------
__device__ float g_proj[6][BT_ * D_];        // 0:qm 1:qc 2:km 3:kc 4:vm 5:vc
__device__ __nv_bfloat16 g_ahi[6][BT_ * D_];
__device__ __nv_bfloat16 g_alo[6][BT_ * D_];
__device__ __nv_bfloat16 g_whi[6][D_ * D_];   // 0:Wk_mean 1:Wk_cov 2:Wv_mean 3:Wv_cov 4:Wo_mean 5:Wo_cov
__device__ __nv_bfloat16 g_wlo[6][D_ * D_];
__device__ __nv_bfloat16 g_chi[2][BT_ * D_];
__device__ __nv_bfloat16 g_clo[2][BT_ * D_];
__device__ float g_qcat[BH_ * 128 * T_];     // [bh][dcat][t]
__device__ float g_kcat[BH_ * 128 * T_];
__device__ float g_vm2[BH_ * T_ * DK_];      // [bh][s][d]
__device__ float g_vc2[BH_ * T_ * DK_];
__device__ float g_bq[BH_ * T_];
__device__ float g_bk[BH_ * T_];
__device__ float g_cm[BT_ * D_];             // attention out (B,T,D)
__device__ float g_cc[BT_ * D_];

// ================= mma.sync helpers (compute_103-safe, no tcgen05) =================
__device__ __forceinline__ uint32_t smem_u32(const void* p) {
    uint32_t a;
    asm("{ .reg .u64 t; cvta.to.shared.u64 t, %1; cvt.u32.u64 %0, t; }" : "=r"(a) : "l"(p));
    return a;
}

__device__ __forceinline__ void ldsm_x4(uint32_t* r, uint32_t addr) {
    asm volatile("ldmatrix.sync.aligned.m8n8.x4.shared.b16 {%0,%1,%2,%3}, [%4];"
                 : "=r"(r[0]), "=r"(r[1]), "=r"(r[2]), "=r"(r[3]) : "r"(addr));
}

__device__ __forceinline__ void mma16816(float* c, const uint32_t* a, const uint32_t* b) {
    asm volatile("mma.sync.aligned.m16n8k16.row.col.f32.bf16.bf16.f32 "
                 "{%0,%1,%2,%3}, {%4,%5,%6,%7}, {%8,%9}, {%0,%1,%2,%3};"
                 : "+f"(c[0]), "+f"(c[1]), "+f"(c[2]), "+f"(c[3])
                 : "r"(a[0]), "r"(a[1]), "r"(a[2]), "r"(a[3]), "r"(b[0]), "r"(b[1]));
}

// swizzled byte offset within a [R][32]-bf16 tile (64B rows, 16B groups)
__device__ __forceinline__ uint32_t swz(uint32_t r, uint32_t g) {
    return r * 64u + ((g ^ ((r >> 1) & 3u)) << 4);
}

// ================= split kernels (fp32 -> bf16 hi/lo) =================
struct SplitIn { const float* src[6]; };

__device__ __forceinline__ void split4(float4 v, __nv_bfloat16* hi, __nv_bfloat16* lo, size_t idx)
{
    float x[4] = {v.x, v.y, v.z, v.w};
    ushort4 hp, lp;
    unsigned short* hpp = &hp.x; unsigned short* lpp = &lp.x;
#pragma unroll
    for (int i = 0; i < 4; i++) {
        __nv_bfloat16 h = __float2bfloat16(x[i]);
        __nv_bfloat16 l = __float2bfloat16(x[i] - __bfloat162float(h));
        hpp[i] = __bfloat16_as_ushort(h);
        lpp[i] = __bfloat16_as_ushort(l);
    }
    *(ushort4*)(hi + idx) = hp;
    *(ushort4*)(lo + idx) = lp;
}

__global__ void split_in(SplitIn si)
{
    int z = blockIdx.y;
    size_t i4 = (size_t)blockIdx.x * 256 + threadIdx.x;
    float4 v = ((const float4*)si.src[z])[i4];
    split4(v, g_ahi[z], g_alo[z], i4 * 4);
}

__global__ void split_w(SplitIn si)
{
    int z = blockIdx.y;
    size_t i4 = (size_t)blockIdx.x * 256 + threadIdx.x;
    float4 v = ((const float4*)si.src[z])[i4];
    split4(v, g_whi[z], g_wlo[z], i4 * 4);
}

__global__ void split_c()
{
    int z = blockIdx.y;
    size_t i4 = (size_t)blockIdx.x * 256 + threadIdx.x;
    float4 v = ((const float4*)(z ? g_cc : g_cm))[i4];
    split4(v, g_chi[z], g_clo[z], i4 * 4);
}

// ================= bf16x3 GEMM via mma.sync =================
// C[8192,512] = A[8192,512] @ W[512,512]^T + bias.
// CTA 128x128, BK=32, 8 warps (2x4), warp tile 64x32.
struct GemmArgs { const float* bias[6]; float* out; int is_out; };

__global__ void __launch_bounds__(256, 2) gemm_mma(GemmArgs ga)
{
    __shared__ __align__(16) char sAhi[8192];
    __shared__ __align__(16) char sAlo[8192];
    __shared__ __align__(16) char sWhi[8192];
    __shared__ __align__(16) char sWlo[8192];

    const int z = blockIdx.z;
    const int n0 = blockIdx.x * 128;
    const int m0 = blockIdx.y * 128;
    const int tid = threadIdx.x;
    const int lane = tid & 31;
    const int w = tid >> 5;
    const int wm = w >> 2;          // 0..1 -> 64 rows
    const int wn = w & 3;           // 0..3 -> 32 cols

    const __nv_bfloat16 *Ah, *Al, *Wh, *Wl;
    const float* bias;
    float* C;
    if (ga.is_out) {
        Ah = g_chi[z]; Al = g_clo[z];
        Wh = g_whi[4 + z]; Wl = g_wlo[4 + z];
        bias = ga.bias[4 + z];
        C = ga.out + (size_t)z * BT_ * D_;
    } else {
        int ws = (z < 4) ? (z & 1) : (z - 2);
        Ah = g_ahi[z]; Al = g_alo[z];
        Wh = g_whi[ws]; Wl = g_wlo[ws];
        bias = ga.bias[ws];
        C = &g_proj[z][0];
    }

    const uint32_t bAhi = smem_u32(sAhi), bAlo = smem_u32(sAlo);
    const uint32_t bWhi = smem_u32(sWhi), bWlo = smem_u32(sWlo);

    float acc[4][4][4];             // [mt][nt][4]
#pragma unroll
    for (int i = 0; i < 4; i++)
#pragma unroll
        for (int j = 0; j < 4; j++)
#pragma unroll
            for (int q = 0; q < 4; q++) acc[i][j][q] = 0.f;

    // per-lane ldmatrix source coordinates
    const int a_r = lane & 15, a_c = lane >> 4;                 // A: row, colblock half
    const int b_r = (lane & 7) + ((lane >> 4) << 3);            // B: n row
    const int b_c = (lane >> 3) & 1;                            // B: colblock half

    for (int kt = 0; kt < 512; kt += 32) {
        __syncthreads();
#pragma unroll
        for (int i = 0; i < 2; i++) {
            int idx = i * 256 + tid;          // 512 uint4 per tile
            uint32_t r = idx >> 2, g = idx & 3;
            uint32_t so = swz(r, g);
            size_t goA = (size_t)(m0 + r) * 512 + kt + g * 8;
            size_t goW = (size_t)(n0 + r) * 512 + kt + g * 8;
            *(uint4*)(sAhi + so) = *(const uint4*)(Ah + goA);
            *(uint4*)(sAlo + so) = *(const uint4*)(Al + goA);
            *(uint4*)(sWhi + so) = *(const uint4*)(Wh + goW);
            *(uint4*)(sWlo + so) = *(const uint4*)(Wl + goW);
        }
        __syncthreads();

#pragma unroll
        for (int ks = 0; ks < 2; ks++) {
            uint32_t bhi[4][2], blo[4][2];
            // B frags: one x4 covers two n-tiles
#pragma unroll
            for (int pr = 0; pr < 2; pr++) {
                uint32_t r = (uint32_t)(wn * 32 + pr * 16 + b_r);
                uint32_t cb = (uint32_t)(ks * 2 + b_c);
                uint32_t t[4];
                ldsm_x4(t, bWhi + swz(r, cb));
                bhi[2 * pr][0] = t[0]; bhi[2 * pr][1] = t[1];
                bhi[2 * pr + 1][0] = t[2]; bhi[2 * pr + 1][1] = t[3];
                ldsm_x4(t, bWlo + swz(r, cb));
                blo[2 * pr][0] = t[0]; blo[2 * pr][1] = t[1];
                blo[2 * pr + 1][0] = t[2]; blo[2 * pr + 1][1] = t[3];
            }
            uint32_t a[4][4];
            {
                uint32_t cb = (uint32_t)(ks * 2 + a_c);
#pragma unroll
                for (int mt = 0; mt < 4; mt++) {
                    uint32_t r = (uint32_t)(wm * 64 + mt * 16 + a_r);
                    ldsm_x4(a[mt], bAhi + swz(r, cb));
                }
            }
#pragma unroll
            for (int mt = 0; mt < 4; mt++)
#pragma unroll
                for (int nt = 0; nt < 4; nt++) {
                    mma16816(acc[mt][nt], a[mt], bhi[nt]);
                    mma16816(acc[mt][nt], a[mt], blo[nt]);
                }
            {
                uint32_t cb = (uint32_t)(ks * 2 + a_c);
#pragma unroll
                for (int mt = 0; mt < 4; mt++) {
                    uint32_t r = (uint32_t)(wm * 64 + mt * 16 + a_r);
                    ldsm_x4(a[mt], bAlo + swz(r, cb));
                }
            }
#pragma unroll
            for (int mt = 0; mt < 4; mt++)
#pragma unroll
                for (int nt = 0; nt < 4; nt++)
                    mma16816(acc[mt][nt], a[mt], bhi[nt]);
        }
    }

    // epilogue: direct global write + bias
    const int g8 = lane >> 2;       // row within 8
    const int t2 = lane & 3;        // col pair
#pragma unroll
    for (int nt = 0; nt < 4; nt++) {
        int col = n0 + wn * 32 + nt * 8 + 2 * t2;
        float2 b2 = *(const float2*)(bias + col);
#pragma unroll
        for (int mt = 0; mt < 4; mt++) {
            int row0 = m0 + wm * 64 + mt * 16 + g8;
            float2 v0 = make_float2(acc[mt][nt][0] + b2.x, acc[mt][nt][1] + b2.y);
            float2 v1 = make_float2(acc[mt][nt][2] + b2.x, acc[mt][nt][3] + b2.y);
            *(float2*)(C + (size_t)row0 * 512 + col) = v0;
            *(float2*)(C + (size_t)(row0 + 8) * 512 + col) = v1;
        }
    }
}

// ---------------- per-(bh,t) bias sums ----------------
__global__ void rowsum_kernel()
{
    int gw = (blockIdx.x * blockDim.x + threadIdx.x) >> 5;
    int lane = threadIdx.x & 31;
    if (gw >= BH_ * T_) return;
    int bh = gw >> 10, t = gw & 1023;
    int b = bh >> 3, h = bh & 7;
    size_t base = (size_t)(b * 1024 + t) * 512 + h * 64;
    float s0 = 0.f, s1 = 0.f, s2 = 0.f, s3 = 0.f;
#pragma unroll
    for (int i = 0; i < 2; i++) {
        int d = lane + 32 * i;
        float a = g_proj[0][base + d]; s0 += a * a;
        s1 += g_proj[1][base + d];
        float c = g_proj[2][base + d]; s2 += c * c;
        s3 += g_proj[3][base + d];
    }
#pragma unroll
    for (int o = 16; o; o >>= 1) {
        s0 += __shfl_xor_sync(0xffffffffu, s0, o);
        s1 += __shfl_xor_sync(0xffffffffu, s1, o);
        s2 += __shfl_xor_sync(0xffffffffu, s2, o);
        s3 += __shfl_xor_sync(0xffffffffu, s3, o);
    }
    if (lane == 0) { g_bq[gw] = s0 + s1; g_bk[gw] = s2 + s3; }
}

// ---------------- pack Q/K into d-major [bh][128][T] ----------------
__global__ void pack_qk()
{
    __shared__ float tile[32][33];
    int bh = blockIdx.z, b = bh >> 3, h = bh & 7;
    int t0 = blockIdx.y * 32;
    int zz = blockIdx.x;
    bool isK = (zz >= 4);
    int dc0 = (zz & 3) * 32;
    const float* srcM = isK ? g_proj[2] : g_proj[0];
    const float* srcC = isK ? g_proj[3] : g_proj[1];
    float* dst = (isK ? g_kcat : g_qcat) + (size_t)bh * 128 * T_;
    int tid = threadIdx.x;

    for (int e = tid; e < 1024; e += 256) {
        int tl = e >> 5, dl = e & 31;
        int dcat = dc0 + dl;
        float v;
        size_t rb = (size_t)(b * 1024 + t0 + tl) * 512 + h * 64;
        if (dcat < 64) v = srcM[rb + dcat];
        else           v = sqrtf(fmaxf(srcC[rb + dcat - 64], 1e-24f));
        tile[tl][dl] = v;
    }
    __syncthreads();
    for (int e = tid; e < 1024; e += 256) {
        int dl = e >> 5, tl = e & 31;
        dst[(size_t)(dc0 + dl) * T_ + t0 + tl] = tile[tl][dl];
    }
}

// ---------------- pack V into [bh][s][64] ----------------
__global__ void pack_v()
{
    int idx = blockIdx.x * 256 + threadIdx.x;
    int d = idx & 63;
    int s = (idx >> 6) & 1023;
    int bh = idx >> 16;
    int b = bh >> 3, h = bh & 7;
    size_t src = (size_t)(b * 1024 + s) * 512 + h * 64 + d;
    g_vm2[idx] = g_proj[4][src];
    g_vc2[idx] = g_proj[5][src];
}

// ---------------- fused attention (fp32) ----------------
#define TR 32
#define ATTN_SMEM ((32 * 1024 + 128 * 32 + 128 * 128 + 128) * 4)

__device__ __forceinline__ float wredmax(float v)
{
#pragma unroll
    for (int o = 16; o; o >>= 1) v = fmaxf(v, __shfl_xor_sync(0xffffffffu, v, o));
    return v;
}
__device__ __forceinline__ float wredsum(float v)
{
#pragma unroll
    for (int o = 16; o; o >>= 1) v += __shfl_xor_sync(0xffffffffu, v, o);
    return v;
}

__global__ void __launch_bounds__(256, 1) attn_kernel(const float* __restrict__ gammas)
{
    float* smem = (float*)dsmem;
    float* sc  = smem;
    float* qs  = sc + 32 * 1024;
    float* ks  = qs + 128 * 32;
    float* bks = ks + 128 * 128;

    const int bh = blockIdx.y;
    const int tile = (int)gridDim.x - 1 - (int)blockIdx.x;
    const int t0 = tile * TR;
    const int tid = threadIdx.x;
    const int lane = tid & 31, warp = tid >> 5;
    const int NT = (t0 + TR + 127) / 128;
    const int Smax = NT * 128;
    const int b = bh >> 3, h = bh & 7;

    const float* Qc = g_qcat + (size_t)bh * 128 * T_;
    const float* Kc = g_kcat + (size_t)bh * 128 * T_;

#pragma unroll
    for (int it = 0; it < 4; it++) {
        int idx = it * 256 + tid;
        int d = idx >> 3, t4 = (idx & 7) * 4;
        float4 v = *(const float4*)(Qc + (size_t)d * T_ + t0 + t4);
        *(float4*)(qs + d * 32 + t4) = v;
    }
    const int tgrp = warp;
    const int sgrp = lane;
    float bq4[4];
    {
        const float* bqp = g_bq + bh * T_ + t0 + 4 * tgrp;
        bq4[0] = bqp[0]; bq4[1] = bqp[1]; bq4[2] = bqp[2]; bq4[3] = bqp[3];
    }

    for (int st = 0; st < NT; st++) {
        const int S0 = st * 128;
        __syncthreads();
#pragma unroll
        for (int it = 0; it < 16; it++) {
            int idx = it * 256 + tid;
            int d = idx >> 5, s4 = (idx & 31) * 4;
            float4 v = *(const float4*)(Kc + (size_t)d * T_ + S0 + s4);
            *(float4*)(ks + d * 128 + s4) = v;
        }
        if (tid < 128) bks[tid] = g_bk[bh * T_ + S0 + tid];
        __syncthreads();

        float acc[4][4];
#pragma unroll
        for (int i = 0; i < 4; i++)
#pragma unroll
            for (int j = 0; j < 4; j++) acc[i][j] = 0.f;

#pragma unroll 8
        for (int d = 0; d < 128; d++) {
            float4 qf = *(const float4*)(qs + d * 32 + 4 * tgrp);
            float4 kf = *(const float4*)(ks + d * 128 + 4 * sgrp);
            float q[4] = {qf.x, qf.y, qf.z, qf.w};
            float k[4] = {kf.x, kf.y, kf.z, kf.w};
#pragma unroll
            for (int i = 0; i < 4; i++)
#pragma unroll
                for (int j = 0; j < 4; j++) acc[i][j] += q[i] * k[j];
        }
        float bk0 = bks[4 * sgrp + 0], bk1 = bks[4 * sgrp + 1];
        float bk2 = bks[4 * sgrp + 2], bk3 = bks[4 * sgrp + 3];
#pragma unroll
        for (int i = 0; i < 4; i++) {
            float4 o;
            o.x = (2.f * acc[i][0] - bq4[i] - bk0) * 0.125f;
            o.y = (2.f * acc[i][1] - bq4[i] - bk1) * 0.125f;
            o.z = (2.f * acc[i][2] - bq4[i] - bk2) * 0.125f;
            o.w = (2.f * acc[i][3] - bq4[i] - bk3) * 0.125f;
            *(float4*)(sc + (4 * tgrp + i) * 1024 + S0 + 4 * sgrp) = o;
        }
    }
    __syncthreads();

    float g = gammas[h];
    float gamma = -(fmaxf(g, 0.f) + log1pf(__expf(-fabsf(g))));

    for (int r = warp; r < TR; r += 8) {
        const int tg = t0 + r;
        float* row = sc + r * 1024;
        const int L = tg + 1;

        float m = -3.4e38f;
        for (int s = lane; s < L; s += 32) m = fmaxf(m, row[s]);
        m = wredmax(m);

        float sum = 0.f;
        for (int s = lane; s < L; s += 32) sum += __expf(row[s] - m);
        sum = wredsum(sum);
        const float inv = 1.f / sum;

        float carry = 0.f, m2 = -3.4e38f;
        const int nch = (L + 31) >> 5;
        for (int c = 0; c < nch; c++) {
            int s = c * 32 + lane;
            bool v = (s < L);
            float x = v ? row[s] : 0.f;
            float e = v ? __expf(x - m) * inv : 0.f;
            float scan = e;
#pragma unroll
            for (int o = 1; o < 32; o <<= 1) {
                float n = __shfl_up_sync(0xffffffffu, scan, o);
                if (lane >= o) scan += n;
            }
            float cum = carry + scan;
            carry += __shfl_sync(0xffffffffu, scan, 31);
            if (v) {
                float pos = (float)(tg - s);
                float ds = sqrtf(fmaxf((1.f - cum) * pos, 0.f));
                float eff = __expf(ds * gamma);
                eff = fminf(fmaxf(eff, 1e-5f), 1e5f);
                float y = x * eff;
                row[s] = y;
                m2 = fmaxf(m2, y);
            }
        }
        m2 = wredmax(m2);

        float s2 = 0.f;
        for (int s = lane; s < L; s += 32) {
            float e = __expf(row[s] - m2);
            row[s] = e;
            s2 += e;
        }
        s2 = wredsum(s2);
        const float inv2 = (tg == 0) ? 0.f : 1.f / s2;
        for (int s = lane; s < Smax; s += 32)
            row[s] = (s < L) ? row[s] * inv2 : 0.f;
    }
    __syncthreads();

    float am[2][4], ac[2][4];
#pragma unroll
    for (int i = 0; i < 2; i++)
#pragma unroll
        for (int j = 0; j < 4; j++) { am[i][j] = 0.f; ac[i][j] = 0.f; }

    const int dgrp = tid & 15;
    const int tg2 = tid >> 4;
    float* vsm = ks;
    float* vsc = ks + 128 * 64;
    const float* Vm = g_vm2 + (size_t)bh * T_ * DK_;
    const float* Vc = g_vc2 + (size_t)bh * T_ * DK_;
    const float* prow0 = sc + (2 * tg2) * 1024;
    const float* prow1 = sc + (2 * tg2 + 1) * 1024;

    for (int st = 0; st < NT; st++) {
        const int S0 = st * 128;
        __syncthreads();
#pragma unroll
        for (int it = 0; it < 8; it++) {
            int idx = it * 256 + tid;
            int s = idx >> 4, d4 = (idx & 15) * 4;
            *(float4*)(vsm + s * 64 + d4) = *(const float4*)(Vm + (size_t)(S0 + s) * 64 + d4);
            *(float4*)(vsc + s * 64 + d4) = *(const float4*)(Vc + (size_t)(S0 + s) * 64 + d4);
        }
        __syncthreads();
#pragma unroll 4
        for (int s = 0; s < 128; s++) {
            float p0 = prow0[S0 + s];
            float p1 = prow1[S0 + s];
            float4 vm4 = *(const float4*)(vsm + s * 64 + 4 * dgrp);
            float4 vc4 = *(const float4*)(vsc + s * 64 + 4 * dgrp);
            float p0s = p0 * p0, p1s = p1 * p1;
            am[0][0] += p0 * vm4.x; am[0][1] += p0 * vm4.y; am[0][2] += p0 * vm4.z; am[0][3] += p0 * vm4.w;
            am[1][0] += p1 * vm4.x; am[1][1] += p1 * vm4.y; am[1][2] += p1 * vm4.z; am[1][3] += p1 * vm4.w;
            ac[0][0] += p0s * vc4.x; ac[0][1] += p0s * vc4.y; ac[0][2] += p0s * vc4.z; ac[0][3] += p0s * vc4.w;
            ac[1][0] += p1s * vc4.x; ac[1][1] += p1s * vc4.y; ac[1][2] += p1s * vc4.z; ac[1][3] += p1s * vc4.w;
        }
    }

    size_t obase = (size_t)(b * 1024 + t0 + 2 * tg2) * 512 + h * 64 + 4 * dgrp;
    *(float4*)(g_cm + obase)       = make_float4(am[0][0], am[0][1], am[0][2], am[0][3]);
    *(float4*)(g_cm + obase + 512) = make_float4(am[1][0], am[1][1], am[1][2], am[1][3]);
    *(float4*)(g_cc + obase)       = make_float4(ac[0][0], ac[0][1], ac[0][2], ac[0][3]);
    *(float4*)(g_cc + obase + 512) = make_float4(ac[1][0], ac[1][1], ac[1][2], ac[1][3]);
}

// ---------------- launch ----------------
extern "C" void kernel_launch(void* const* d_in, const int* in_sizes, int n_in,
                              void* d_out, int out_size)
{
    const float* q_mean  = (const float*)d_in[0];
    const float* q_cov   = (const float*)d_in[1];
    const float* k_mean  = (const float*)d_in[2];
    const float* k_cov   = (const float*)d_in[3];
    const float* v_mean  = (const float*)d_in[4];
    const float* v_cov   = (const float*)d_in[5];
    const float* Wk_mean = (const float*)d_in[6];
    const float* bk_mean = (const float*)d_in[7];
    const float* Wk_cov  = (const float*)d_in[8];
    const float* bk_cov  = (const float*)d_in[9];
    const float* Wv_mean = (const float*)d_in[10];
    const float* bv_mean = (const float*)d_in[11];
    const float* Wv_cov  = (const float*)d_in[12];
    const float* bv_cov  = (const float*)d_in[13];
    const float* Wo_mean = (const float*)d_in[14];
    const float* bo_mean = (const float*)d_in[15];
    const float* Wo_cov  = (const float*)d_in[16];
    const float* bo_cov  = (const float*)d_in[17];
    const float* gammas  = (const float*)d_in[18];
    float* out = (float*)d_out;

    // split weights + inputs to bf16 hi/lo
    SplitIn sw;
    sw.src[0] = Wk_mean; sw.src[1] = Wk_cov; sw.src[2] = Wv_mean;
    sw.src[3] = Wv_cov;  sw.src[4] = Wo_mean; sw.src[5] = Wo_cov;
    split_w<<<dim3(D_ * D_ / 1024, 6), 256>>>(sw);

    SplitIn sa;
    sa.src[0] = q_mean; sa.src[1] = q_cov; sa.src[2] = k_mean;
    sa.src[3] = k_cov;  sa.src[4] = v_mean; sa.src[5] = v_cov;
    split_in<<<dim3(BT_ * D_ / 1024, 6), 256>>>(sa);

    GemmArgs gp;
    gp.bias[0] = bk_mean; gp.bias[1] = bk_cov; gp.bias[2] = bv_mean;
    gp.bias[3] = bv_cov;  gp.bias[4] = bo_mean; gp.bias[5] = bo_cov;
    gp.out = nullptr; gp.is_out = 0;
    gemm_mma<<<dim3(4, 64, 6), 256>>>(gp);

    rowsum_kernel<<<(BH_ * T_ * 32) / 256, 256>>>();
    pack_qk<<<dim3(8, 32, 64), 256>>>();
    pack_v<<<(BH_ * T_ * DK_) / 256, 256>>>();

    cudaFuncSetAttribute(attn_kernel, cudaFuncAttributeMaxDynamicSharedMemorySize, ATTN_SMEM);
    attn_kernel<<<dim3(32, 64), 256, ATTN_SMEM>>>(gammas);

    split_c<<<dim3(BT_ * D_ / 1024, 2), 256>>>();

    GemmArgs go = gp;
    go.out = out; go.is_out = 1;
    gemm_mma<<<dim3(4, 64, 2), 256>>>(go);
}

// round 5
// speedup vs baseline: 1.6684x; 1.3452x over previous
#include <cuda_runtime.h>
#include <cuda_bf16.h>
#include <math.h>
#include <stdint.h>

// Problem constants
#define B_  8
#define T_  1024
#define D_  512
#define H_  8
#define DK_ 64
#define BT_ 8192      // B*T
#define BH_ 64        // B*H

// single dynamic-smem symbol (attention kernel only)
extern __shared__ char dsmem[];

// ---------------- scratch (device globals; no allocation allowed) ----------------
__device__ float g_proj[6][BT_ * D_];        // 0:qm 1:qc 2:km 3:kc 4:vm 5:vc
__device__ __nv_bfloat16 g_ahi[6][BT_ * D_];
__device__ __nv_bfloat16 g_alo[6][BT_ * D_];
__device__ __nv_bfloat16 g_whi[6][D_ * D_];
__device__ __nv_bfloat16 g_wlo[6][D_ * D_];
__device__ __nv_bfloat16 g_chi[2][BT_ * D_];
__device__ __nv_bfloat16 g_clo[2][BT_ * D_];
// attention operands (bf16 hi/lo)
__device__ unsigned short g_qh[BH_ * T_ * 128];   // [bh][t][dcat] K-major
__device__ unsigned short g_ql[BH_ * T_ * 128];
__device__ unsigned short g_kh[BH_ * T_ * 128];
__device__ unsigned short g_kl[BH_ * T_ * 128];
__device__ unsigned short g_vmh[BH_ * DK_ * T_]; // [bh][d][s] (V transposed)
__device__ unsigned short g_vml[BH_ * DK_ * T_];
__device__ unsigned short g_vch[BH_ * DK_ * T_];
__device__ unsigned short g_vcl[BH_ * DK_ * T_];
__device__ float g_bq[BH_ * T_];
__device__ float g_bk[BH_ * T_];
__device__ float g_cm[BT_ * D_];             // attention out (B,T,D)
__device__ float g_cc[BT_ * D_];

// ================= mma.sync helpers =================
__device__ __forceinline__ uint32_t smem_u32(const void* p) {
    uint32_t a;
    asm("{ .reg .u64 t; cvta.to.shared.u64 t, %1; cvt.u32.u64 %0, t; }" : "=r"(a) : "l"(p));
    return a;
}
__device__ __forceinline__ void ldsm_x4(uint32_t* r, uint32_t addr) {
    asm volatile("ldmatrix.sync.aligned.m8n8.x4.shared.b16 {%0,%1,%2,%3}, [%4];"
                 : "=r"(r[0]), "=r"(r[1]), "=r"(r[2]), "=r"(r[3]) : "r"(addr));
}
__device__ __forceinline__ void mma16816(float* c, const uint32_t* a, const uint32_t* b) {
    asm volatile("mma.sync.aligned.m16n8k16.row.col.f32.bf16.bf16.f32 "
                 "{%0,%1,%2,%3}, {%4,%5,%6,%7}, {%8,%9}, {%0,%1,%2,%3};"
                 : "+f"(c[0]), "+f"(c[1]), "+f"(c[2]), "+f"(c[3])
                 : "r"(a[0]), "r"(a[1]), "r"(a[2]), "r"(a[3]), "r"(b[0]), "r"(b[1]));
}
// swizzle for [R][32]-bf16 tiles (64B rows) — used by gemm_mma
__device__ __forceinline__ uint32_t swz(uint32_t r, uint32_t g) {
    return r * 64u + ((g ^ ((r >> 1) & 3u)) << 4);
}
// swizzle for [R][128]-bf16 tiles (256B rows) — used by attn
__device__ __forceinline__ uint32_t swz128(uint32_t r, uint32_t g) {
    return r * 256u + ((g ^ (r & 7u)) << 4);
}
__device__ __forceinline__ void bf16split(float x, unsigned short& h, unsigned short& l) {
    __nv_bfloat16 hb = __float2bfloat16(x);
    __nv_bfloat16 lb = __float2bfloat16(x - __bfloat162float(hb));
    h = __bfloat16_as_ushort(hb);
    l = __bfloat16_as_ushort(lb);
}

// ================= split kernels (fp32 -> bf16 hi/lo) =================
struct SplitIn { const float* src[6]; };

__device__ __forceinline__ void split4(float4 v, __nv_bfloat16* hi, __nv_bfloat16* lo, size_t idx)
{
    float x[4] = {v.x, v.y, v.z, v.w};
    ushort4 hp, lp;
    unsigned short* hpp = &hp.x; unsigned short* lpp = &lp.x;
#pragma unroll
    for (int i = 0; i < 4; i++) {
        unsigned short h, l;
        bf16split(x[i], h, l);
        hpp[i] = h; lpp[i] = l;
    }
    *(ushort4*)(hi + idx) = hp;
    *(ushort4*)(lo + idx) = lp;
}

__global__ void split_in(SplitIn si)
{
    int z = blockIdx.y;
    size_t i4 = (size_t)blockIdx.x * 256 + threadIdx.x;
    float4 v = ((const float4*)si.src[z])[i4];
    split4(v, g_ahi[z], g_alo[z], i4 * 4);
}

__global__ void split_w(SplitIn si)
{
    int z = blockIdx.y;
    size_t i4 = (size_t)blockIdx.x * 256 + threadIdx.x;
    float4 v = ((const float4*)si.src[z])[i4];
    split4(v, g_whi[z], g_wlo[z], i4 * 4);
}

__global__ void split_c()
{
    int z = blockIdx.y;
    size_t i4 = (size_t)blockIdx.x * 256 + threadIdx.x;
    float4 v = ((const float4*)(z ? g_cc : g_cm))[i4];
    split4(v, g_chi[z], g_clo[z], i4 * 4);
}

// ================= bf16x3 GEMM via mma.sync (unchanged from R4) =================
struct GemmArgs { const float* bias[6]; float* out; int is_out; };

__global__ void __launch_bounds__(256, 2) gemm_mma(GemmArgs ga)
{
    __shared__ __align__(16) char sAhi[8192];
    __shared__ __align__(16) char sAlo[8192];
    __shared__ __align__(16) char sWhi[8192];
    __shared__ __align__(16) char sWlo[8192];

    const int z = blockIdx.z;
    const int n0 = blockIdx.x * 128;
    const int m0 = blockIdx.y * 128;
    const int tid = threadIdx.x;
    const int lane = tid & 31;
    const int w = tid >> 5;
    const int wm = w >> 2;
    const int wn = w & 3;

    const __nv_bfloat16 *Ah, *Al, *Wh, *Wl;
    const float* bias;
    float* C;
    if (ga.is_out) {
        Ah = g_chi[z]; Al = g_clo[z];
        Wh = g_whi[4 + z]; Wl = g_wlo[4 + z];
        bias = ga.bias[4 + z];
        C = ga.out + (size_t)z * BT_ * D_;
    } else {
        int ws = (z < 4) ? (z & 1) : (z - 2);
        Ah = g_ahi[z]; Al = g_alo[z];
        Wh = g_whi[ws]; Wl = g_wlo[ws];
        bias = ga.bias[ws];
        C = &g_proj[z][0];
    }

    const uint32_t bAhi = smem_u32(sAhi), bAlo = smem_u32(sAlo);
    const uint32_t bWhi = smem_u32(sWhi), bWlo = smem_u32(sWlo);

    float acc[4][4][4];
#pragma unroll
    for (int i = 0; i < 4; i++)
#pragma unroll
        for (int j = 0; j < 4; j++)
#pragma unroll
            for (int q = 0; q < 4; q++) acc[i][j][q] = 0.f;

    const int a_r = lane & 15, a_c = lane >> 4;
    const int b_r = (lane & 7) + ((lane >> 4) << 3);
    const int b_c = (lane >> 3) & 1;

    for (int kt = 0; kt < 512; kt += 32) {
        __syncthreads();
#pragma unroll
        for (int i = 0; i < 2; i++) {
            int idx = i * 256 + tid;
            uint32_t r = idx >> 2, g = idx & 3;
            uint32_t so = swz(r, g);
            size_t goA = (size_t)(m0 + r) * 512 + kt + g * 8;
            size_t goW = (size_t)(n0 + r) * 512 + kt + g * 8;
            *(uint4*)(sAhi + so) = *(const uint4*)(Ah + goA);
            *(uint4*)(sAlo + so) = *(const uint4*)(Al + goA);
            *(uint4*)(sWhi + so) = *(const uint4*)(Wh + goW);
            *(uint4*)(sWlo + so) = *(const uint4*)(Wl + goW);
        }
        __syncthreads();

#pragma unroll
        for (int ks = 0; ks < 2; ks++) {
            uint32_t bhi[4][2], blo[4][2];
#pragma unroll
            for (int pr = 0; pr < 2; pr++) {
                uint32_t r = (uint32_t)(wn * 32 + pr * 16 + b_r);
                uint32_t cb = (uint32_t)(ks * 2 + b_c);
                uint32_t t[4];
                ldsm_x4(t, bWhi + swz(r, cb));
                bhi[2 * pr][0] = t[0]; bhi[2 * pr][1] = t[1];
                bhi[2 * pr + 1][0] = t[2]; bhi[2 * pr + 1][1] = t[3];
                ldsm_x4(t, bWlo + swz(r, cb));
                blo[2 * pr][0] = t[0]; blo[2 * pr][1] = t[1];
                blo[2 * pr + 1][0] = t[2]; blo[2 * pr + 1][1] = t[3];
            }
            uint32_t a[4][4];
            {
                uint32_t cb = (uint32_t)(ks * 2 + a_c);
#pragma unroll
                for (int mt = 0; mt < 4; mt++) {
                    uint32_t r = (uint32_t)(wm * 64 + mt * 16 + a_r);
                    ldsm_x4(a[mt], bAhi + swz(r, cb));
                }
            }
#pragma unroll
            for (int mt = 0; mt < 4; mt++)
#pragma unroll
                for (int nt = 0; nt < 4; nt++) {
                    mma16816(acc[mt][nt], a[mt], bhi[nt]);
                    mma16816(acc[mt][nt], a[mt], blo[nt]);
                }
            {
                uint32_t cb = (uint32_t)(ks * 2 + a_c);
#pragma unroll
                for (int mt = 0; mt < 4; mt++) {
                    uint32_t r = (uint32_t)(wm * 64 + mt * 16 + a_r);
                    ldsm_x4(a[mt], bAlo + swz(r, cb));
                }
            }
#pragma unroll
            for (int mt = 0; mt < 4; mt++)
#pragma unroll
                for (int nt = 0; nt < 4; nt++)
                    mma16816(acc[mt][nt], a[mt], bhi[nt]);
        }
    }

    const int g8 = lane >> 2;
    const int t2 = lane & 3;
#pragma unroll
    for (int nt = 0; nt < 4; nt++) {
        int col = n0 + wn * 32 + nt * 8 + 2 * t2;
        float2 b2 = *(const float2*)(bias + col);
#pragma unroll
        for (int mt = 0; mt < 4; mt++) {
            int row0 = m0 + wm * 64 + mt * 16 + g8;
            float2 v0 = make_float2(acc[mt][nt][0] + b2.x, acc[mt][nt][1] + b2.y);
            float2 v1 = make_float2(acc[mt][nt][2] + b2.x, acc[mt][nt][3] + b2.y);
            *(float2*)(C + (size_t)row0 * 512 + col) = v0;
            *(float2*)(C + (size_t)(row0 + 8) * 512 + col) = v1;
        }
    }
}

// ---------------- per-(bh,t) bias sums ----------------
__global__ void rowsum_kernel()
{
    int gw = (blockIdx.x * blockDim.x + threadIdx.x) >> 5;
    int lane = threadIdx.x & 31;
    if (gw >= BH_ * T_) return;
    int bh = gw >> 10, t = gw & 1023;
    int b = bh >> 3, h = bh & 7;
    size_t base = (size_t)(b * 1024 + t) * 512 + h * 64;
    float s0 = 0.f, s1 = 0.f, s2 = 0.f, s3 = 0.f;
#pragma unroll
    for (int i = 0; i < 2; i++) {
        int d = lane + 32 * i;
        float a = g_proj[0][base + d]; s0 += a * a;
        s1 += g_proj[1][base + d];
        float c = g_proj[2][base + d]; s2 += c * c;
        s3 += g_proj[3][base + d];
    }
#pragma unroll
    for (int o = 16; o; o >>= 1) {
        s0 += __shfl_xor_sync(0xffffffffu, s0, o);
        s1 += __shfl_xor_sync(0xffffffffu, s1, o);
        s2 += __shfl_xor_sync(0xffffffffu, s2, o);
        s3 += __shfl_xor_sync(0xffffffffu, s3, o);
    }
    if (lane == 0) { g_bq[gw] = s0 + s1; g_bk[gw] = s2 + s3; }
}

// ---------------- pack Q/K concat into bf16 hi/lo [bh][t][128] ----------------
__global__ void pack_qk()
{
    int idx = blockIdx.x * 256 + threadIdx.x;     // 64*1024*16
    int g = idx & 15;
    int t = (idx >> 4) & 1023;
    int bh = idx >> 14;
    int b = bh >> 3, h = bh & 7;
    size_t base = (size_t)(b * 1024 + t) * 512 + h * 64;

    float qv[8], kv[8];
    if (g < 8) {
#pragma unroll
        for (int j = 0; j < 8; j++) {
            qv[j] = g_proj[0][base + g * 8 + j];
            kv[j] = g_proj[2][base + g * 8 + j];
        }
    } else {
#pragma unroll
        for (int j = 0; j < 8; j++) {
            qv[j] = sqrtf(fmaxf(g_proj[1][base + (g - 8) * 8 + j], 1e-24f));
            kv[j] = sqrtf(fmaxf(g_proj[3][base + (g - 8) * 8 + j], 1e-24f));
        }
    }
    unsigned short qh8[8], ql8[8], kh8[8], kl8[8];
#pragma unroll
    for (int j = 0; j < 8; j++) {
        bf16split(qv[j], qh8[j], ql8[j]);
        bf16split(kv[j], kh8[j], kl8[j]);
    }
    size_t o = ((size_t)(bh * 1024 + t)) * 128 + g * 8;
    *(uint4*)(g_qh + o) = *(uint4*)qh8;
    *(uint4*)(g_ql + o) = *(uint4*)ql8;
    *(uint4*)(g_kh + o) = *(uint4*)kh8;
    *(uint4*)(g_kl + o) = *(uint4*)kl8;
}

// ---------------- pack V transposed into bf16 hi/lo [bh][d][s] ----------------
__global__ void pack_v()
{
    __shared__ float tile[32][65];
    int s0 = blockIdx.x * 32;
    int z = blockIdx.y;               // 0: mean, 1: cov
    int bh = blockIdx.z;
    int b = bh >> 3, h = bh & 7;
    const float* src = g_proj[4 + z];
    int tid = threadIdx.x;

#pragma unroll
    for (int e = 0; e < 8; e++) {
        int idx = e * 256 + tid;          // 2048 = 32 s x 64 d
        int sl = idx >> 6, d = idx & 63;
        tile[sl][d] = src[(size_t)(b * 1024 + s0 + sl) * 512 + h * 64 + d];
    }
    __syncthreads();
    unsigned short* dh = z ? g_vch : g_vmh;
    unsigned short* dl = z ? g_vcl : g_vml;
#pragma unroll
    for (int e = 0; e < 8; e++) {
        int idx = e * 256 + tid;
        int d = idx >> 5, sl = idx & 31;
        unsigned short hh, ll;
        bf16split(tile[sl][d], hh, ll);
        size_t o = ((size_t)(bh * 64 + d)) * 1024 + s0 + sl;
        dh[o] = hh;
        dl[o] = ll;
    }
}

// ---------------- fused attention (mma.sync score + PV) ----------------
#define TR 32
#define SC_STRIDE 1028
#define STG_OFF (32 * SC_STRIDE * 4)          // 131584
#define ATTN_SMEM (STG_OFF + 98304)           // 229888

__device__ __forceinline__ float wredmax(float v)
{
#pragma unroll
    for (int o = 16; o; o >>= 1) v = fmaxf(v, __shfl_xor_sync(0xffffffffu, v, o));
    return v;
}
__device__ __forceinline__ float wredsum(float v)
{
#pragma unroll
    for (int o = 16; o; o >>= 1) v += __shfl_xor_sync(0xffffffffu, v, o);
    return v;
}

__global__ void __launch_bounds__(256, 1) attn_kernel(const float* __restrict__ gammas)
{
    char* smem = dsmem;
    float* sc = (float*)smem;
    char* stg = smem + STG_OFF;

    const int bh = blockIdx.y;
    const int tile = (int)gridDim.x - 1 - (int)blockIdx.x;
    const int t0 = tile * TR;
    const int tid = threadIdx.x;
    const int lane = tid & 31, w = tid >> 5;
    const int NT = (t0 + TR + 127) / 128;
    const int Smax = NT * 128;
    const int b = bh >> 3, h = bh & 7;

    const int a_r = lane & 15, a_c = lane >> 4;
    const int b_r = (lane & 7) + ((lane >> 4) << 3);
    const int b_c = (lane >> 3) & 1;
    const int g8 = lane >> 2, t2 = lane & 3;

    // staging addresses
    const uint32_t sb = smem_u32(stg);
    const uint32_t aQh = sb, aQl = sb + 8192, aKh = sb + 16384, aKl = sb + 49152;
    const uint32_t aPh = sb, aPl = sb + 8192, aP2h = sb + 16384, aP2l = sb + 24576;
    const uint32_t aVmh = sb + 32768, aVml = sb + 49152, aVch = sb + 65536, aVcl = sb + 81920;

    // ---- load Q tile (hi/lo, swizzled) ----
    {
        const unsigned short* Qh = g_qh + ((size_t)(bh * 1024 + t0)) * 128;
        const unsigned short* Ql = g_ql + ((size_t)(bh * 1024 + t0)) * 128;
#pragma unroll
        for (int it = 0; it < 4; it++) {
            int idx = it * 256 + tid;         // 1024: 512 hi + 512 lo
            int half = idx >> 9;
            uint32_t r = (idx >> 4) & 31, g = idx & 15;
            const unsigned short* src = (half ? Ql : Qh) + r * 128 + g * 8;
            *(uint4*)(stg + half * 8192 + swz128(r, g)) = *(const uint4*)src;
        }
    }
    // per-thread bq for score epilogue rows
    float bqv[2][2];
#pragma unroll
    for (int mt = 0; mt < 2; mt++) {
        bqv[mt][0] = g_bq[bh * T_ + t0 + mt * 16 + g8];
        bqv[mt][1] = g_bq[bh * T_ + t0 + mt * 16 + g8 + 8];
    }

    // ==================== score phase ====================
    for (int st = 0; st < NT; st++) {
        const int S0 = st * 128;
        __syncthreads();
        {
            const unsigned short* Kh = g_kh + ((size_t)(bh * 1024 + S0)) * 128;
            const unsigned short* Kl = g_kl + ((size_t)(bh * 1024 + S0)) * 128;
#pragma unroll
            for (int it = 0; it < 16; it++) {
                int idx = it * 256 + tid;     // 4096: 2048 hi + 2048 lo
                int half = idx >> 11;
                uint32_t r = (idx >> 4) & 127, g = idx & 15;
                const unsigned short* src = (half ? Kl : Kh) + r * 128 + g * 8;
                *(uint4*)(stg + 16384 + half * 32768 + swz128(r, g)) = *(const uint4*)src;
            }
        }
        __syncthreads();

        float acc[2][2][4];
#pragma unroll
        for (int i = 0; i < 2; i++)
#pragma unroll
            for (int j = 0; j < 2; j++)
#pragma unroll
                for (int q = 0; q < 4; q++) acc[i][j][q] = 0.f;

#pragma unroll
        for (int ks = 0; ks < 8; ks++) {
            uint32_t cbA = (uint32_t)(ks * 2 + a_c);
            uint32_t cbB = (uint32_t)(ks * 2 + b_c);
            uint32_t ah[2][4], al[2][4];
#pragma unroll
            for (int mt = 0; mt < 2; mt++) {
                ldsm_x4(ah[mt], aQh + swz128((uint32_t)(mt * 16 + a_r), cbA));
                ldsm_x4(al[mt], aQl + swz128((uint32_t)(mt * 16 + a_r), cbA));
            }
            uint32_t t4[4], bhf[2][2], blf[2][2];
            ldsm_x4(t4, aKh + swz128((uint32_t)(w * 16 + b_r), cbB));
            bhf[0][0] = t4[0]; bhf[0][1] = t4[1]; bhf[1][0] = t4[2]; bhf[1][1] = t4[3];
            ldsm_x4(t4, aKl + swz128((uint32_t)(w * 16 + b_r), cbB));
            blf[0][0] = t4[0]; blf[0][1] = t4[1]; blf[1][0] = t4[2]; blf[1][1] = t4[3];
#pragma unroll
            for (int mt = 0; mt < 2; mt++)
#pragma unroll
                for (int nt = 0; nt < 2; nt++) {
                    mma16816(acc[mt][nt], ah[mt], bhf[nt]);
                    mma16816(acc[mt][nt], ah[mt], blf[nt]);
                    mma16816(acc[mt][nt], al[mt], bhf[nt]);
                }
        }
        // epilogue: scores = 0.25*dot - 0.125*(bq+bk)
#pragma unroll
        for (int nt = 0; nt < 2; nt++) {
            int col = w * 16 + nt * 8 + 2 * t2;
            float2 bk2 = *(const float2*)(g_bk + bh * T_ + S0 + col);
#pragma unroll
            for (int mt = 0; mt < 2; mt++) {
                int row = mt * 16 + g8;
                float2 v0, v1;
                v0.x = 0.25f * acc[mt][nt][0] - 0.125f * (bqv[mt][0] + bk2.x);
                v0.y = 0.25f * acc[mt][nt][1] - 0.125f * (bqv[mt][0] + bk2.y);
                v1.x = 0.25f * acc[mt][nt][2] - 0.125f * (bqv[mt][1] + bk2.x);
                v1.y = 0.25f * acc[mt][nt][3] - 0.125f * (bqv[mt][1] + bk2.y);
                *(float2*)(sc + (size_t)row * SC_STRIDE + S0 + col) = v0;
                *(float2*)(sc + (size_t)(row + 8) * SC_STRIDE + S0 + col) = v1;
            }
        }
    }
    __syncthreads();

    // ==================== softmax -> cumsum decay -> softmax ====================
    float g = gammas[h];
    float gamma = -(fmaxf(g, 0.f) + log1pf(__expf(-fabsf(g))));

    for (int r = w; r < TR; r += 8) {
        const int tg = t0 + r;
        float* row = sc + (size_t)r * SC_STRIDE;
        const int L = tg + 1;

        float m = -3.4e38f;
        for (int s = lane; s < L; s += 32) m = fmaxf(m, row[s]);
        m = wredmax(m);

        float sum = 0.f;
        for (int s = lane; s < L; s += 32) sum += __expf(row[s] - m);
        sum = wredsum(sum);
        const float inv = 1.f / sum;

        float carry = 0.f, m2 = -3.4e38f;
        const int nch = (L + 31) >> 5;
        for (int c = 0; c < nch; c++) {
            int s = c * 32 + lane;
            bool v = (s < L);
            float x = v ? row[s] : 0.f;
            float e = v ? __expf(x - m) * inv : 0.f;
            float scan = e;
#pragma unroll
            for (int o = 1; o < 32; o <<= 1) {
                float n = __shfl_up_sync(0xffffffffu, scan, o);
                if (lane >= o) scan += n;
            }
            float cum = carry + scan;
            carry += __shfl_sync(0xffffffffu, scan, 31);
            if (v) {
                float pos = (float)(tg - s);
                float ds = sqrtf(fmaxf((1.f - cum) * pos, 0.f));
                float eff = __expf(ds * gamma);
                eff = fminf(fmaxf(eff, 1e-5f), 1e5f);
                float y = x * eff;
                row[s] = y;
                m2 = fmaxf(m2, y);
            }
        }
        m2 = wredmax(m2);

        float s2 = 0.f;
        for (int s = lane; s < L; s += 32) {
            float e = __expf(row[s] - m2);
            row[s] = e;
            s2 += e;
        }
        s2 = wredsum(s2);
        const float inv2 = (tg == 0) ? 0.f : 1.f / s2;
        for (int s = lane; s < Smax; s += 32)
            row[s] = (s < L) ? row[s] * inv2 : 0.f;
    }
    __syncthreads();

    // ==================== PV phase (mma.sync) ====================
    const int wm = w >> 2;          // 0..1 (m-tile)
    const int wn = w & 3;           // 0..3 (16-d column group)
    float am[2][4], acv[2][4];
#pragma unroll
    for (int i = 0; i < 2; i++)
#pragma unroll
        for (int q = 0; q < 4; q++) { am[i][q] = 0.f; acv[i][q] = 0.f; }

    const unsigned short* Vmh = g_vmh + (size_t)bh * DK_ * T_;
    const unsigned short* Vml = g_vml + (size_t)bh * DK_ * T_;
    const unsigned short* Vch = g_vch + (size_t)bh * DK_ * T_;
    const unsigned short* Vcl = g_vcl + (size_t)bh * DK_ * T_;

    for (int st = 0; st < NT; st++) {
        const int S0 = st * 128;
        __syncthreads();
        // convert P chunk -> bf16 hi/lo + P^2 hi/lo
#pragma unroll
        for (int e = 0; e < 2; e++) {
            int idx = e * 256 + tid;          // 512 = 32 rows x 16 groups
            uint32_t r = (uint32_t)(idx >> 4), gg = (uint32_t)(idx & 15);
            const float* p8 = sc + (size_t)r * SC_STRIDE + S0 + gg * 8;
            unsigned short ph[8], pl[8], qh2[8], ql2[8];
#pragma unroll
            for (int j = 0; j < 8; j++) {
                float p = p8[j];
                bf16split(p, ph[j], pl[j]);
                bf16split(p * p, qh2[j], ql2[j]);
            }
            uint32_t so = swz128(r, gg);
            *(uint4*)(stg + so) = *(uint4*)ph;
            *(uint4*)(stg + 8192 + so) = *(uint4*)pl;
            *(uint4*)(stg + 16384 + so) = *(uint4*)qh2;
            *(uint4*)(stg + 24576 + so) = *(uint4*)ql2;
        }
        // load V tiles [64][128] x4 arrays
#pragma unroll
        for (int it = 0; it < 16; it++) {
            int idx = it * 256 + tid;         // 4096
            int arr = idx >> 10;
            uint32_t r = (uint32_t)((idx >> 4) & 63), gg = (uint32_t)(idx & 15);
            const unsigned short* src =
                (arr == 0 ? Vmh : arr == 1 ? Vml : arr == 2 ? Vch : Vcl) + (size_t)r * T_ + S0 + gg * 8;
            *(uint4*)(stg + 32768 + arr * 16384 + swz128(r, gg)) = *(const uint4*)src;
        }
        __syncthreads();

#pragma unroll
        for (int ks = 0; ks < 8; ks++) {
            uint32_t cbA = (uint32_t)(ks * 2 + a_c);
            uint32_t cbB = (uint32_t)(ks * 2 + b_c);
            uint32_t ap[4], al2[4], a2p[4], a2l[4];
            uint32_t ra = (uint32_t)(wm * 16 + a_r);
            ldsm_x4(ap,  aPh  + swz128(ra, cbA));
            ldsm_x4(al2, aPl  + swz128(ra, cbA));
            ldsm_x4(a2p, aP2h + swz128(ra, cbA));
            ldsm_x4(a2l, aP2l + swz128(ra, cbA));

            uint32_t t4[4], bmh[2][2], bml[2][2], bch[2][2], bcl[2][2];
            uint32_t rb = (uint32_t)(wn * 16 + b_r);
            ldsm_x4(t4, aVmh + swz128(rb, cbB));
            bmh[0][0] = t4[0]; bmh[0][1] = t4[1]; bmh[1][0] = t4[2]; bmh[1][1] = t4[3];
            ldsm_x4(t4, aVml + swz128(rb, cbB));
            bml[0][0] = t4[0]; bml[0][1] = t4[1]; bml[1][0] = t4[2]; bml[1][1] = t4[3];
            ldsm_x4(t4, aVch + swz128(rb, cbB));
            bch[0][0] = t4[0]; bch[0][1] = t4[1]; bch[1][0] = t4[2]; bch[1][1] = t4[3];
            ldsm_x4(t4, aVcl + swz128(rb, cbB));
            bcl[0][0] = t4[0]; bcl[0][1] = t4[1]; bcl[1][0] = t4[2]; bcl[1][1] = t4[3];

#pragma unroll
            for (int nt = 0; nt < 2; nt++) {
                mma16816(am[nt], ap, bmh[nt]);
                mma16816(am[nt], ap, bml[nt]);
                mma16816(am[nt], al2, bmh[nt]);
                mma16816(acv[nt], a2p, bch[nt]);
                mma16816(acv[nt], a2p, bcl[nt]);
                mma16816(acv[nt], a2l, bch[nt]);
            }
        }
    }

    // write outputs (B,T,D)
#pragma unroll
    for (int nt = 0; nt < 2; nt++) {
        int col = h * 64 + wn * 16 + nt * 8 + 2 * t2;
#pragma unroll
        for (int half = 0; half < 2; half++) {
            int trow = t0 + wm * 16 + g8 + half * 8;
            size_t o = (size_t)(b * 1024 + trow) * 512 + col;
            *(float2*)(g_cm + o) = make_float2(am[nt][half * 2], am[nt][half * 2 + 1]);
            *(float2*)(g_cc + o) = make_float2(acv[nt][half * 2], acv[nt][half * 2 + 1]);
        }
    }
}

// ---------------- launch ----------------
extern "C" void kernel_launch(void* const* d_in, const int* in_sizes, int n_in,
                              void* d_out, int out_size)
{
    const float* q_mean  = (const float*)d_in[0];
    const float* q_cov   = (const float*)d_in[1];
    const float* k_mean  = (const float*)d_in[2];
    const float* k_cov   = (const float*)d_in[3];
    const float* v_mean  = (const float*)d_in[4];
    const float* v_cov   = (const float*)d_in[5];
    const float* Wk_mean = (const float*)d_in[6];
    const float* bk_mean = (const float*)d_in[7];
    const float* Wk_cov  = (const float*)d_in[8];
    const float* bk_cov  = (const float*)d_in[9];
    const float* Wv_mean = (const float*)d_in[10];
    const float* bv_mean = (const float*)d_in[11];
    const float* Wv_cov  = (const float*)d_in[12];
    const float* bv_cov  = (const float*)d_in[13];
    const float* Wo_mean = (const float*)d_in[14];
    const float* bo_mean = (const float*)d_in[15];
    const float* Wo_cov  = (const float*)d_in[16];
    const float* bo_cov  = (const float*)d_in[17];
    const float* gammas  = (const float*)d_in[18];
    float* out = (float*)d_out;

    SplitIn sw;
    sw.src[0] = Wk_mean; sw.src[1] = Wk_cov; sw.src[2] = Wv_mean;
    sw.src[3] = Wv_cov;  sw.src[4] = Wo_mean; sw.src[5] = Wo_cov;
    split_w<<<dim3(D_ * D_ / 1024, 6), 256>>>(sw);

    SplitIn sa;
    sa.src[0] = q_mean; sa.src[1] = q_cov; sa.src[2] = k_mean;
    sa.src[3] = k_cov;  sa.src[4] = v_mean; sa.src[5] = v_cov;
    split_in<<<dim3(BT_ * D_ / 1024, 6), 256>>>(sa);

    GemmArgs gp;
    gp.bias[0] = bk_mean; gp.bias[1] = bk_cov; gp.bias[2] = bv_mean;
    gp.bias[3] = bv_cov;  gp.bias[4] = bo_mean; gp.bias[5] = bo_cov;
    gp.out = nullptr; gp.is_out = 0;
    gemm_mma<<<dim3(4, 64, 6), 256>>>(gp);

    rowsum_kernel<<<(BH_ * T_ * 32) / 256, 256>>>();
    pack_qk<<<(BH_ * T_ * 16) / 256, 256>>>();
    pack_v<<<dim3(32, 2, 64), 256>>>();

    cudaFuncSetAttribute(attn_kernel, cudaFuncAttributeMaxDynamicSharedMemorySize, ATTN_SMEM);
    attn_kernel<<<dim3(32, 64), 256, ATTN_SMEM>>>(gammas);

    split_c<<<dim3(BT_ * D_ / 1024, 2), 256>>>();

    GemmArgs go = gp;
    go.out = out; go.is_out = 1;
    gemm_mma<<<dim3(4, 64, 2), 256>>>(go);
}